// round 9
// baseline (speedup 1.0000x reference)
#include <cuda_runtime.h>

#define RS2 0.7071067811865476f
#define TAU_V 0.05f

constexpr int SH  = 34;              // even, ≡2 mod 32
constexpr int SD  = 1090;            // even, ≡2 mod 32
constexpr int SH2 = 17;              // strides in float2 units
constexpr int SD2 = 545;
constexpr int TILE_F = 32 * SD;      // 34880 floats = 139520 B
constexpr int NTHREADS = 512;

// valid level-1 band-block slots (slot = d3*16 + h3*4 + w3, excluding lll octant)
__device__ __constant__ unsigned char VSLOT[56] = {
    2,3,6,7,8,9,10,11,12,13,14,15,18,19,22,23,
    24,25,26,27,28,29,30,31,32,33,34,35,36,37,38,39,
    40,41,42,43,44,45,46,47,48,49,50,51,52,53,54,55,
    56,57,58,59,60,61,62,63
};

extern __shared__ float smem[];

__device__ __forceinline__ float2 f2add(float2 a, float2 b) {
    return make_float2((a.x + b.x) * RS2, (a.y + b.y) * RS2);
}
__device__ __forceinline__ float2 f2sub(float2 a, float2 b) {
    return make_float2((a.x - b.x) * RS2, (a.y - b.y) * RS2);
}

// ---- h/d pass over pairs of adjacent w columns (float2), in place ----
template<int N, int NA, int NW2, int SBASE2, int SLINE2, bool FWD>
__device__ __forceinline__ void pass_hd(float2* T2, int tid) {
    constexpr int NL = NA * NW2;
    if (NL >= NTHREADS || tid < NL) {
        int a = tid / NW2, wp = tid - a * NW2;
        float2* p = T2 + a * SBASE2 + wp;
        float2 v[N];
#pragma unroll
        for (int k = 0; k < N; k++) v[k] = p[k * SLINE2];
#pragma unroll
        for (int i = 0; i < N / 2; i++) {
            if (FWD) {
                p[i * SLINE2]         = f2add(v[2*i], v[2*i+1]);
                p[(i + N/2) * SLINE2] = f2sub(v[2*i], v[2*i+1]);
            } else {
                p[(2*i) * SLINE2]     = f2add(v[i], v[i + N/2]);
                p[(2*i + 1) * SLINE2] = f2sub(v[i], v[i + N/2]);
            }
        }
    }
}

// ---- level-2 w pass: 16-long lines along w at (d,h) in [0,16)^2, all-float2 ----
template<bool FWD>
__device__ __forceinline__ void pass_w16(float2* T2, int tid) {
    if (tid < 256) {
        int d = tid >> 4, h = tid & 15;
        float2* p = T2 + d * SD2 + h * SH2;
        float2 q[8];
#pragma unroll
        for (int k = 0; k < 8; k++) q[k] = p[k];
        if (FWD) {
#pragma unroll
            for (int t = 0; t < 4; t++) {
                float2 lo, hi;
                lo.x = (q[2*t].x   + q[2*t].y)   * RS2;
                lo.y = (q[2*t+1].x + q[2*t+1].y) * RS2;
                hi.x = (q[2*t].x   - q[2*t].y)   * RS2;
                hi.y = (q[2*t+1].x - q[2*t+1].y) * RS2;
                p[t] = lo; p[4 + t] = hi;
            }
        } else {
#pragma unroll
            for (int t = 0; t < 4; t++) {
                float2 lo = q[t], hi = q[4 + t];
                p[2*t]     = make_float2((lo.x + hi.x) * RS2, (lo.x - hi.x) * RS2);
                p[2*t + 1] = make_float2((lo.y + hi.y) * RS2, (lo.y - hi.y) * RS2);
            }
        }
    }
}

// ---- 2D Haar pyramid fwd + soft-threshold + inv on v[64] in registers ----
__device__ __forceinline__ void pyramid(float* v) {
#pragma unroll
    for (int lev = 0; lev < 3; lev++) {
        const int S = 8 >> lev, H = S >> 1;
#pragma unroll
        for (int j = 0; j < S; j++) {
            float t[4], u[4];
#pragma unroll
            for (int i = 0; i < H; i++) {
                float a = v[(2*i)*8+j], b = v[(2*i+1)*8+j];
                t[i] = (a + b) * RS2; u[i] = (a - b) * RS2;
            }
#pragma unroll
            for (int i = 0; i < H; i++) { v[i*8+j] = t[i]; v[(i+H)*8+j] = u[i]; }
        }
#pragma unroll
        for (int i = 0; i < S; i++) {
            float t[4], u[4];
#pragma unroll
            for (int j = 0; j < H; j++) {
                float a = v[i*8+2*j], b = v[i*8+2*j+1];
                t[j] = (a + b) * RS2; u[j] = (a - b) * RS2;
            }
#pragma unroll
            for (int j = 0; j < H; j++) { v[i*8+j] = t[j]; v[i*8+j+H] = u[j]; }
        }
    }
#pragma unroll
    for (int e = 1; e < 64; e++)
        v[e] = copysignf(fmaxf(fabsf(v[e]) - TAU_V, 0.0f), v[e]);
#pragma unroll
    for (int lev = 2; lev >= 0; lev--) {
        const int S = 8 >> lev, H = S >> 1;
#pragma unroll
        for (int i = 0; i < S; i++) {
            float t[4], u[4];
#pragma unroll
            for (int j = 0; j < H; j++) {
                float lo = v[i*8+j], hi = v[i*8+j+H];
                t[j] = (lo + hi) * RS2; u[j] = (lo - hi) * RS2;
            }
#pragma unroll
            for (int j = 0; j < H; j++) { v[i*8+2*j] = t[j]; v[i*8+2*j+1] = u[j]; }
        }
#pragma unroll
        for (int j = 0; j < S; j++) {
            float t[4], u[4];
#pragma unroll
            for (int i = 0; i < H; i++) {
                float lo = v[i*8+j], hi = v[(i+H)*8+j];
                t[i] = (lo + hi) * RS2; u[i] = (lo - hi) * RS2;
            }
#pragma unroll
            for (int i = 0; i < H; i++) { v[(2*i)*8+j] = t[i]; v[(2*i+1)*8+j] = u[i]; }
        }
    }
}

// ---- one block processed by ONE warp: lanes 0-23 = (normal, slice); warp-local ordering only ----
__device__ void bandlet_block_warp(float* T, int lane, int bd, int bh, int bw) {
    const int nrm = lane >> 3;       // 0,1,2 active; 3 = idle lanes 24-31
    const int s   = lane & 7;
    const bool active = (nrm < 3);
    float v[64];
    if (active) {
        if (nrm == 0) {
            const float2* p = reinterpret_cast<const float2*>(T + (bd+s)*SD + bh*SH + bw);
#pragma unroll
            for (int i = 0; i < 8; i++)
#pragma unroll
                for (int jp = 0; jp < 4; jp++) {
                    float2 q = p[i*SH2 + jp];
                    v[i*8 + 2*jp] = q.x; v[i*8 + 2*jp + 1] = q.y;
                }
        } else if (nrm == 1) {
            const float2* p = reinterpret_cast<const float2*>(T + bd*SD + (bh+s)*SH + bw);
#pragma unroll
            for (int i = 0; i < 8; i++)
#pragma unroll
                for (int jp = 0; jp < 4; jp++) {
                    float2 q = p[i*SD2 + jp];
                    v[i*8 + 2*jp] = q.x; v[i*8 + 2*jp + 1] = q.y;
                }
        } else {
            const float* p = T + bd*SD + bh*SH + bw + s;
#pragma unroll
            for (int i = 0; i < 8; i++)
#pragma unroll
                for (int j = 0; j < 8; j++) v[i*8+j] = p[i*SD + j*SH];
        }
        pyramid(v);
    }
    __syncwarp();                    // all reads of original band data complete
    if (nrm == 0) {
        float2* p = reinterpret_cast<float2*>(T + (bd+s)*SD + bh*SH + bw);
#pragma unroll
        for (int i = 0; i < 8; i++)
#pragma unroll
            for (int jp = 0; jp < 4; jp++)
                p[i*SH2 + jp] = make_float2(v[i*8 + 2*jp], v[i*8 + 2*jp + 1]);
    }
    __syncwarp();                    // n0 visible
    if (nrm == 1) {
        float2* p = reinterpret_cast<float2*>(T + bd*SD + (bh+s)*SH + bw);
#pragma unroll
        for (int i = 0; i < 8; i++)
#pragma unroll
            for (int jp = 0; jp < 4; jp++) {
                float2 q = p[i*SD2 + jp];
                q.x += v[i*8 + 2*jp]; q.y += v[i*8 + 2*jp + 1];
                p[i*SD2 + jp] = q;
            }
    }
    __syncwarp();                    // n0+n1 visible
    if (nrm == 2) {
        float* p = T + bd*SD + bh*SH + bw + s;
#pragma unroll
        for (int i = 0; i < 8; i++)
#pragma unroll
            for (int j = 0; j < 8; j++)
                p[i*SD + j*SH] = (p[i*SD + j*SH] + v[i*8+j]) * (1.0f / 3.0f);
    }
    // no trailing sync: the next block handled by this warp is a disjoint region
}

__global__ __launch_bounds__(NTHREADS, 1)
void bandlet3d_kernel(const float* __restrict__ x, float* __restrict__ y) {
    float* T = smem;
    float2* T2 = reinterpret_cast<float2*>(smem);
    const int tid = threadIdx.x;
    const int wid = tid >> 5, lane = tid & 31;

    const int bc = blockIdx.x;
    const int batch = bc / 125;
    const int rem = bc - batch * 125;
    const int td = rem / 25;
    const int th = (rem / 5) % 5;
    const int tw = rem % 5;
    const long long gbase = (long long)batch * 4096000LL
                          + (long long)td * 32 * 25600 + th * 32 * 160 + tw * 32;

    // ---- fused coalesced load + level-1 w-transform ----
    for (int l = tid; l < 8192; l += NTHREADS) {
        int w4 = l & 7, h = (l >> 3) & 31, d = l >> 8;
        float4 q = *reinterpret_cast<const float4*>(x + gbase + d*25600 + h*160 + w4*4);
        float2* p = T2 + d*SD2 + h*SH2;
        p[w4]     = make_float2((q.x + q.y) * RS2, (q.z + q.w) * RS2);
        p[w4 + 8] = make_float2((q.x - q.y) * RS2, (q.z - q.w) * RS2);
    }
    __syncthreads();

    // forward level-1 h and d
    pass_hd<32, 32, 16, SD2, SH2, true>(T2, tid); __syncthreads();
    pass_hd<32, 32, 16, SH2, SD2, true>(T2, tid); __syncthreads();

    // ---- level-1 bandlet: one warp per block, no global barriers ----
    // warps 0-15 take blocks VSLOT[r*16+wid] for r=0,1,2; warps 8-15 take the 8 extra
    // (warps 0-7 also run the level-2 w-pass right after).
#pragma unroll 1
    for (int r = 0; r < 3; r++) {
        int slot = VSLOT[r * 16 + wid];
        int bd = ((slot >> 4) & 3) * 8;
        int bh = ((slot >> 2) & 3) * 8;
        int bw = (slot & 3) * 8;
        bandlet_block_warp(T, lane, bd, bh, bw);
    }
    if (wid >= 8) {
        int slot = VSLOT[40 + wid];          // 48 + (wid - 8)
        int bd = ((slot >> 4) & 3) * 8;
        int bh = ((slot >> 2) & 3) * 8;
        int bw = (slot & 3) * 8;
        bandlet_block_warp(T, lane, bd, bh, bw);
    }
    // no global barrier: fwd level-2 (below) touches only the lll region, disjoint
    // from every band block; the following __syncthreads joins everything.

    // forward level-2 (w, h, d on [0:16)^3)
    pass_w16<true>(T2, tid);                       __syncthreads();
    pass_hd<16, 16, 8, SD2, SH2, true>(T2, tid);   __syncthreads();
    pass_hd<16, 16, 8, SH2, SD2, true>(T2, tid);   __syncthreads();

    // ---- level-2 bandlet: 7 blocks on warps 0-6, warp-local ordering only ----
    if (wid < 7) {
        int slot = wid + 1;
        int bd = ((slot >> 2) & 1) * 8;
        int bh = ((slot >> 1) & 1) * 8;
        int bw = (slot & 1) * 8;
        bandlet_block_warp(T, lane, bd, bh, bw);
    }
    __syncthreads();   // idwt level-2 reads the band blocks just written

    // inverse level-2 (w, h, d)
    pass_w16<false>(T2, tid);                      __syncthreads();
    pass_hd<16, 16, 8, SD2, SH2, false>(T2, tid);  __syncthreads();
    pass_hd<16, 16, 8, SH2, SD2, false>(T2, tid);  __syncthreads();

    // inverse level-1: d, h, then w fused with the store
    pass_hd<32, 32, 16, SH2, SD2, false>(T2, tid); __syncthreads();
    pass_hd<32, 32, 16, SD2, SH2, false>(T2, tid); __syncthreads();

    // ---- fused inverse level-1 w-transform + coalesced store ----
    for (int l = tid; l < 8192; l += NTHREADS) {
        int w4 = l & 7, h = (l >> 3) & 31, d = l >> 8;
        const float2* p = T2 + d*SD2 + h*SH2;
        float2 lo = p[w4], hi = p[w4 + 8];
        float4 q;
        q.x = (lo.x + hi.x) * RS2; q.y = (lo.x - hi.x) * RS2;
        q.z = (lo.y + hi.y) * RS2; q.w = (lo.y - hi.y) * RS2;
        *reinterpret_cast<float4*>(y + gbase + d*25600 + h*160 + w4*4) = q;
    }
}

extern "C" void kernel_launch(void* const* d_in, const int* in_sizes, int n_in,
                              void* d_out, int out_size) {
    const float* x = (const float*)d_in[0];
    float* y = (float*)d_out;
    (void)in_sizes; (void)n_in; (void)out_size;

    const size_t smem_bytes = (size_t)TILE_F * sizeof(float); // 139520 B
    cudaFuncSetAttribute(bandlet3d_kernel,
                         cudaFuncAttributeMaxDynamicSharedMemorySize, (int)smem_bytes);
    bandlet3d_kernel<<<250, NTHREADS, smem_bytes>>>(x, y);
}

// round 10
// speedup vs baseline: 1.0575x; 1.0575x over previous
#include <cuda_runtime.h>

#define RS2 0.7071067811865476f
#define TAU_V 0.05f

constexpr int SH  = 34;              // even, ≡2 mod 32
constexpr int SD  = 1090;            // even, ≡2 mod 32
constexpr int SH2 = 17;              // strides in float2 units
constexpr int SD2 = 545;
constexpr int TILE_F = 32 * SD;      // 34880 floats
constexpr int SBF  = 514;            // scratch block stride (floats), ≡2 mod 32
constexpr int SBF2 = 257;            // in float2 units
constexpr int NBLK_MAX = 21;
constexpr int SCR_F = 2 * NBLK_MAX * SBF;   // 21588 floats
constexpr int NTHREADS = 512;

// valid level-1 band-block slots (slot = d3*16 + h3*4 + w3, excluding lll octant)
__device__ __constant__ unsigned char VSLOT[56] = {
    2,3,6,7,8,9,10,11,12,13,14,15,18,19,22,23,
    24,25,26,27,28,29,30,31,32,33,34,35,36,37,38,39,
    40,41,42,43,44,45,46,47,48,49,50,51,52,53,54,55,
    56,57,58,59,60,61,62,63
};

extern __shared__ float smem[];

__device__ __forceinline__ float2 f2add(float2 a, float2 b) {
    return make_float2((a.x + b.x) * RS2, (a.y + b.y) * RS2);
}
__device__ __forceinline__ float2 f2sub(float2 a, float2 b) {
    return make_float2((a.x - b.x) * RS2, (a.y - b.y) * RS2);
}

// ---- h/d pass over pairs of adjacent w columns (float2), in place ----
template<int N, int NA, int NW2, int SBASE2, int SLINE2, bool FWD>
__device__ __forceinline__ void pass_hd(float2* T2, int tid) {
    constexpr int NL = NA * NW2;
    if (NL >= NTHREADS || tid < NL) {
        int a = tid / NW2, wp = tid - a * NW2;
        float2* p = T2 + a * SBASE2 + wp;
        float2 v[N];
#pragma unroll
        for (int k = 0; k < N; k++) v[k] = p[k * SLINE2];
#pragma unroll
        for (int i = 0; i < N / 2; i++) {
            if (FWD) {
                p[i * SLINE2]         = f2add(v[2*i], v[2*i+1]);
                p[(i + N/2) * SLINE2] = f2sub(v[2*i], v[2*i+1]);
            } else {
                p[(2*i) * SLINE2]     = f2add(v[i], v[i + N/2]);
                p[(2*i + 1) * SLINE2] = f2sub(v[i], v[i + N/2]);
            }
        }
    }
}

// ---- level-2 w pass: 16-long lines along w at (d,h) in [0,16)^2, all-float2 ----
template<bool FWD>
__device__ __forceinline__ void pass_w16(float2* T2, int tid) {
    if (tid < 256) {
        int d = tid >> 4, h = tid & 15;
        float2* p = T2 + d * SD2 + h * SH2;
        float2 q[8];
#pragma unroll
        for (int k = 0; k < 8; k++) q[k] = p[k];
        if (FWD) {
#pragma unroll
            for (int t = 0; t < 4; t++) {
                float2 lo, hi;
                lo.x = (q[2*t].x   + q[2*t].y)   * RS2;
                lo.y = (q[2*t+1].x + q[2*t+1].y) * RS2;
                hi.x = (q[2*t].x   - q[2*t].y)   * RS2;
                hi.y = (q[2*t+1].x - q[2*t+1].y) * RS2;
                p[t] = lo; p[4 + t] = hi;
            }
        } else {
#pragma unroll
            for (int t = 0; t < 4; t++) {
                float2 lo = q[t], hi = q[4 + t];
                p[2*t]     = make_float2((lo.x + hi.x) * RS2, (lo.x - hi.x) * RS2);
                p[2*t + 1] = make_float2((lo.y + hi.y) * RS2, (lo.y - hi.y) * RS2);
            }
        }
    }
}

// ---- 2D Haar pyramid fwd + soft-threshold + inv on v[64] in registers ----
__device__ __forceinline__ void pyramid(float* v) {
#pragma unroll
    for (int lev = 0; lev < 3; lev++) {
        const int S = 8 >> lev, H = S >> 1;
#pragma unroll
        for (int j = 0; j < S; j++) {
            float t[4], u[4];
#pragma unroll
            for (int i = 0; i < H; i++) {
                float a = v[(2*i)*8+j], b = v[(2*i+1)*8+j];
                t[i] = (a + b) * RS2; u[i] = (a - b) * RS2;
            }
#pragma unroll
            for (int i = 0; i < H; i++) { v[i*8+j] = t[i]; v[(i+H)*8+j] = u[i]; }
        }
#pragma unroll
        for (int i = 0; i < S; i++) {
            float t[4], u[4];
#pragma unroll
            for (int j = 0; j < H; j++) {
                float a = v[i*8+2*j], b = v[i*8+2*j+1];
                t[j] = (a + b) * RS2; u[j] = (a - b) * RS2;
            }
#pragma unroll
            for (int j = 0; j < H; j++) { v[i*8+j] = t[j]; v[i*8+j+H] = u[j]; }
        }
    }
#pragma unroll
    for (int e = 1; e < 64; e++)
        v[e] = copysignf(fmaxf(fabsf(v[e]) - TAU_V, 0.0f), v[e]);
#pragma unroll
    for (int lev = 2; lev >= 0; lev--) {
        const int S = 8 >> lev, H = S >> 1;
#pragma unroll
        for (int i = 0; i < S; i++) {
            float t[4], u[4];
#pragma unroll
            for (int j = 0; j < H; j++) {
                float lo = v[i*8+j], hi = v[i*8+j+H];
                t[j] = (lo + hi) * RS2; u[j] = (lo - hi) * RS2;
            }
#pragma unroll
            for (int j = 0; j < H; j++) { v[i*8+2*j] = t[j]; v[i*8+2*j+1] = u[j]; }
        }
#pragma unroll
        for (int j = 0; j < S; j++) {
            float t[4], u[4];
#pragma unroll
            for (int i = 0; i < H; i++) {
                float lo = v[i*8+j], hi = v[(i+H)*8+j];
                t[i] = (lo + hi) * RS2; u[i] = (lo - hi) * RS2;
            }
#pragma unroll
            for (int i = 0; i < H; i++) { v[(2*i)*8+j] = t[i]; v[(2*i+1)*8+j] = u[i]; }
        }
    }
}

// ---- one bandlet group: p1 compute(all), p2 store (n0->T, n1->S1, n2->S2), p3 balanced merge ----
// Two internal barriers; NO trailing barrier (next group touches disjoint block regions,
// and scratch reuse is fenced by the next group's p1-end barrier).
template<bool LEVEL1>
__device__ __forceinline__ void bandlet_section(float* T, float2* T2, float2* S1, float2* S2,
                                                int tid, int nblk, int base) {
    const int ntask = nblk * 8;
    int nrm = 0, s = 0, bg = 0, bd = 0, bh = 0, bw = 0;
    const bool active = tid < 3 * ntask;
    if (active) {
        nrm = tid / ntask;                      // warp-uniform except 2 boundary warps
        int r = tid - nrm * ntask;
        bg = r >> 3; s = r & 7;
        int slot = LEVEL1 ? (int)VSLOT[base + bg] : (bg + 1);
        if (LEVEL1) {
            bd = ((slot >> 4) & 3) * 8; bh = ((slot >> 2) & 3) * 8; bw = (slot & 3) * 8;
        } else {
            bd = ((slot >> 2) & 1) * 8; bh = ((slot >> 1) & 1) * 8; bw = (slot & 1) * 8;
        }
    }
    float v[64];
    if (active) {
        if (nrm == 0) {
            const float2* p = reinterpret_cast<const float2*>(T + (bd+s)*SD + bh*SH + bw);
#pragma unroll
            for (int i = 0; i < 8; i++)
#pragma unroll
                for (int jp = 0; jp < 4; jp++) {
                    float2 q = p[i*SH2 + jp];
                    v[i*8 + 2*jp] = q.x; v[i*8 + 2*jp + 1] = q.y;
                }
        } else if (nrm == 1) {
            const float2* p = reinterpret_cast<const float2*>(T + bd*SD + (bh+s)*SH + bw);
#pragma unroll
            for (int i = 0; i < 8; i++)
#pragma unroll
                for (int jp = 0; jp < 4; jp++) {
                    float2 q = p[i*SD2 + jp];
                    v[i*8 + 2*jp] = q.x; v[i*8 + 2*jp + 1] = q.y;
                }
        } else {
            const float* p = T + bd*SD + bh*SH + bw + s;
#pragma unroll
            for (int i = 0; i < 8; i++)
#pragma unroll
                for (int j = 0; j < 8; j++) v[i*8+j] = p[i*SD + j*SH];
        }
        pyramid(v);
    }
    __syncthreads();   // all reads of original band data complete

    // p2: everyone stores simultaneously to disjoint destinations
    if (active) {
        if (nrm == 0) {
            float2* p = reinterpret_cast<float2*>(T + (bd+s)*SD + bh*SH + bw);
#pragma unroll
            for (int i = 0; i < 8; i++)
#pragma unroll
                for (int jp = 0; jp < 4; jp++)
                    p[i*SH2 + jp] = make_float2(v[i*8 + 2*jp], v[i*8 + 2*jp + 1]);
        } else {
            // n1: element (a,b,c)=(i,s,j) at S1[bg*SBF + a*64 + b*8 + c]
            // n2: element (a,b,c)=(i,j,s) at S2[bg*SBF + a*64 + c*8 + b]
            // both reduce to the same writer offset: bg*SBF2 + i*32 + s*4 + jp (float2)
            float2* q = ((nrm == 1) ? S1 : S2) + bg * SBF2 + s * 4;
#pragma unroll
            for (int i = 0; i < 8; i++)
#pragma unroll
                for (int jp = 0; jp < 4; jp++)
                    q[i*32 + jp] = make_float2(v[i*8 + 2*jp], v[i*8 + 2*jp + 1]);
        }
    }
    __syncthreads();   // n0 (T) and n1/n2 (S) visible

    // p3: balanced merge T = (T + S1 + S2)/3, all 512 threads, hoisted addressing
    {
        const int hi = tid >> 8;                 // 0 or 1
        const int f2 = tid & 255;                // invariant across k (512 ≡ 0 mod 256)
        const int a  = f2 >> 5, b = (f2 >> 2) & 7, jp = f2 & 3;
        const int off2  = a * SD2 + b * SH2 + jp;
        const int s2off = a * 64 + jp * 16 + b;  // element (a,b,2jp) in (a,c,b) layout
        const float* s2f = reinterpret_cast<const float*>(S2);
        for (int bgm = hi; bgm < nblk; bgm += 2) {
            int slot = LEVEL1 ? (int)VSLOT[base + bgm] : (bgm + 1);
            int obd, obh, obw;
            if (LEVEL1) {
                obd = ((slot >> 4) & 3) * 8; obh = ((slot >> 2) & 3) * 8; obw = (slot & 3) * 8;
            } else {
                obd = ((slot >> 2) & 1) * 8; obh = ((slot >> 1) & 1) * 8; obw = (slot & 1) * 8;
            }
            float2* pt = T2 + obd * SD2 + obh * SH2 + (obw >> 1) + off2;
            float2 tv = *pt;
            float2 s1 = S1[bgm * SBF2 + f2];
            float s2a = s2f[bgm * SBF + s2off];
            float s2b = s2f[bgm * SBF + s2off + 8];
            tv.x = (tv.x + s1.x + s2a) * (1.0f / 3.0f);
            tv.y = (tv.y + s1.y + s2b) * (1.0f / 3.0f);
            *pt = tv;
        }
    }
    // no trailing barrier
}

__global__ __launch_bounds__(NTHREADS, 1)
void bandlet3d_kernel(const float* __restrict__ x, float* __restrict__ y) {
    float* T = smem;
    float2* T2 = reinterpret_cast<float2*>(smem);
    float2* S1 = reinterpret_cast<float2*>(smem + TILE_F);
    float2* S2 = S1 + NBLK_MAX * SBF2;
    const int tid = threadIdx.x;

    const int bc = blockIdx.x;
    const int batch = bc / 125;
    const int rem = bc - batch * 125;
    const int td = rem / 25;
    const int th = (rem / 5) % 5;
    const int tw = rem % 5;
    const long long gbase = (long long)batch * 4096000LL
                          + (long long)td * 32 * 25600 + th * 32 * 160 + tw * 32;

    // ---- fused coalesced load + level-1 w-transform ----
    for (int l = tid; l < 8192; l += NTHREADS) {
        int w4 = l & 7, h = (l >> 3) & 31, d = l >> 8;
        float4 q = *reinterpret_cast<const float4*>(x + gbase + d*25600 + h*160 + w4*4);
        float2* p = T2 + d*SD2 + h*SH2;
        p[w4]     = make_float2((q.x + q.y) * RS2, (q.z + q.w) * RS2);
        p[w4 + 8] = make_float2((q.x - q.y) * RS2, (q.z - q.w) * RS2);
    }
    __syncthreads();

    // forward level-1 h and d
    pass_hd<32, 32, 16, SD2, SH2, true>(T2, tid); __syncthreads();
    pass_hd<32, 32, 16, SH2, SD2, true>(T2, tid); __syncthreads();

    // ---- level-1 bandlet: 56 blocks in groups of 21/21/14, thread-parallel normals ----
    bandlet_section<true>(T, T2, S1, S2, tid, 21, 0);
    bandlet_section<true>(T, T2, S1, S2, tid, 21, 21);
    bandlet_section<true>(T, T2, S1, S2, tid, 14, 42);
    // no barrier: fwd level-2 touches only the lll region (disjoint from band blocks)

    // forward level-2 (w, h, d on [0:16)^3)
    pass_w16<true>(T2, tid);                       __syncthreads();
    pass_hd<16, 16, 8, SD2, SH2, true>(T2, tid);   __syncthreads();
    pass_hd<16, 16, 8, SH2, SD2, true>(T2, tid);   __syncthreads();

    // ---- level-2 bandlet: 7 blocks ----
    bandlet_section<false>(T, T2, S1, S2, tid, 7, 0);
    __syncthreads();   // idwt level-2 reads the band blocks just merged

    // inverse level-2 (w, h, d)
    pass_w16<false>(T2, tid);                      __syncthreads();
    pass_hd<16, 16, 8, SD2, SH2, false>(T2, tid);  __syncthreads();
    pass_hd<16, 16, 8, SH2, SD2, false>(T2, tid);  __syncthreads();

    // inverse level-1: d, h, then w fused with the store
    pass_hd<32, 32, 16, SH2, SD2, false>(T2, tid); __syncthreads();
    pass_hd<32, 32, 16, SD2, SH2, false>(T2, tid); __syncthreads();

    // ---- fused inverse level-1 w-transform + coalesced store ----
    for (int l = tid; l < 8192; l += NTHREADS) {
        int w4 = l & 7, h = (l >> 3) & 31, d = l >> 8;
        const float2* p = T2 + d*SD2 + h*SH2;
        float2 lo = p[w4], hi = p[w4 + 8];
        float4 q;
        q.x = (lo.x + hi.x) * RS2; q.y = (lo.x - hi.x) * RS2;
        q.z = (lo.y + hi.y) * RS2; q.w = (lo.y - hi.y) * RS2;
        *reinterpret_cast<float4*>(y + gbase + d*25600 + h*160 + w4*4) = q;
    }
}

extern "C" void kernel_launch(void* const* d_in, const int* in_sizes, int n_in,
                              void* d_out, int out_size) {
    const float* x = (const float*)d_in[0];
    float* y = (float*)d_out;
    (void)in_sizes; (void)n_in; (void)out_size;

    const size_t smem_bytes = (size_t)(TILE_F + SCR_F) * sizeof(float); // 225872 B
    cudaFuncSetAttribute(bandlet3d_kernel,
                         cudaFuncAttributeMaxDynamicSharedMemorySize, (int)smem_bytes);
    bandlet3d_kernel<<<250, NTHREADS, smem_bytes>>>(x, y);
}

// round 11
// speedup vs baseline: 1.1283x; 1.0670x over previous
#include <cuda_runtime.h>

#define RS2 0.7071067811865476f
#define TAU_V 0.05f

constexpr int SH  = 34;              // even, ≡2 mod 32
constexpr int SD  = 1090;            // even, ≡2 mod 32
constexpr int SH2 = 17;              // strides in float2 units
constexpr int SD2 = 545;
constexpr int TILE_F = 32 * SD;      // 34880 floats = 139520 B
constexpr int NTHREADS = 512;

// valid level-1 band-block slots (slot = d3*16 + h3*4 + w3, excluding lll octant)
__device__ __constant__ unsigned char VSLOT[56] = {
    2,3,6,7,8,9,10,11,12,13,14,15,18,19,22,23,
    24,25,26,27,28,29,30,31,32,33,34,35,36,37,38,39,
    40,41,42,43,44,45,46,47,48,49,50,51,52,53,54,55,
    56,57,58,59,60,61,62,63
};

extern __shared__ float smem[];

__device__ __forceinline__ void barA() { asm volatile("bar.sync 1, 128;" ::: "memory"); }
__device__ __forceinline__ void barB() { asm volatile("bar.sync 2, 384;" ::: "memory"); }
template<int G> __device__ __forceinline__ void gbar() { if (G == 1) barA(); else barB(); }

__device__ __forceinline__ float2 f2add(float2 a, float2 b) {
    return make_float2((a.x + b.x) * RS2, (a.y + b.y) * RS2);
}
__device__ __forceinline__ float2 f2sub(float2 a, float2 b) {
    return make_float2((a.x - b.x) * RS2, (a.y - b.y) * RS2);
}

// in-place float2 Haar line transform along stride SLINE2
template<int N, int SLINE2, bool FWD>
__device__ __forceinline__ void line_f2(float2* p) {
    float2 v[N];
#pragma unroll
    for (int k = 0; k < N; k++) v[k] = p[k * SLINE2];
#pragma unroll
    for (int i = 0; i < N / 2; i++) {
        if (FWD) {
            p[i * SLINE2]         = f2add(v[2*i], v[2*i+1]);
            p[(i + N/2) * SLINE2] = f2sub(v[2*i], v[2*i+1]);
        } else {
            p[(2*i) * SLINE2]     = f2add(v[i], v[i + N/2]);
            p[(2*i + 1) * SLINE2] = f2sub(v[i], v[i + N/2]);
        }
    }
}

// ---- full-width (512-thread) level-1 h/d pass ----
template<int SBASE2, int SLINE2, bool FWD>
__device__ __forceinline__ void pass_l1(float2* T2, int tid) {
    int a = tid >> 4, wp = tid & 15;
    line_f2<32, SLINE2, FWD>(T2 + a * SBASE2 + wp);
}

// ---- level-2 passes on 128 threads (group A) ----
template<bool FWD>
__device__ __forceinline__ void l2_pass_w(float2* T2, int g) {
#pragma unroll
    for (int l = g; l < 256; l += 128) {
        int d = l >> 4, h = l & 15;
        float2* p = T2 + d * SD2 + h * SH2;
        float2 q[8];
#pragma unroll
        for (int k = 0; k < 8; k++) q[k] = p[k];
        if (FWD) {
#pragma unroll
            for (int t = 0; t < 4; t++) {
                float2 lo, hi;
                lo.x = (q[2*t].x   + q[2*t].y)   * RS2;
                lo.y = (q[2*t+1].x + q[2*t+1].y) * RS2;
                hi.x = (q[2*t].x   - q[2*t].y)   * RS2;
                hi.y = (q[2*t+1].x - q[2*t+1].y) * RS2;
                p[t] = lo; p[4 + t] = hi;
            }
        } else {
#pragma unroll
            for (int t = 0; t < 4; t++) {
                float2 lo = q[t], hi = q[4 + t];
                p[2*t]     = make_float2((lo.x + hi.x) * RS2, (lo.x - hi.x) * RS2);
                p[2*t + 1] = make_float2((lo.y + hi.y) * RS2, (lo.y - hi.y) * RS2);
            }
        }
    }
}
template<bool FWD>
__device__ __forceinline__ void l2_pass_h(float2* T2, int g) {   // 128 lines (d, wp)
    int d = g >> 3, wp = g & 7;
    line_f2<16, SH2, FWD>(T2 + d * SD2 + wp);
}
template<bool FWD>
__device__ __forceinline__ void l2_pass_d(float2* T2, int g) {   // 128 lines (h, wp)
    int h = g >> 3, wp = g & 7;
    line_f2<16, SD2, FWD>(T2 + h * SH2 + wp);
}

// ---- 2D Haar pyramid fwd + soft-threshold + inv on v[64] in registers ----
__device__ __forceinline__ void pyramid(float* v) {
#pragma unroll
    for (int lev = 0; lev < 3; lev++) {
        const int S = 8 >> lev, H = S >> 1;
#pragma unroll
        for (int j = 0; j < S; j++) {
            float t[4], u[4];
#pragma unroll
            for (int i = 0; i < H; i++) {
                float a = v[(2*i)*8+j], b = v[(2*i+1)*8+j];
                t[i] = (a + b) * RS2; u[i] = (a - b) * RS2;
            }
#pragma unroll
            for (int i = 0; i < H; i++) { v[i*8+j] = t[i]; v[(i+H)*8+j] = u[i]; }
        }
#pragma unroll
        for (int i = 0; i < S; i++) {
            float t[4], u[4];
#pragma unroll
            for (int j = 0; j < H; j++) {
                float a = v[i*8+2*j], b = v[i*8+2*j+1];
                t[j] = (a + b) * RS2; u[j] = (a - b) * RS2;
            }
#pragma unroll
            for (int j = 0; j < H; j++) { v[i*8+j] = t[j]; v[i*8+j+H] = u[j]; }
        }
    }
#pragma unroll
    for (int e = 1; e < 64; e++)
        v[e] = copysignf(fmaxf(fabsf(v[e]) - TAU_V, 0.0f), v[e]);
#pragma unroll
    for (int lev = 2; lev >= 0; lev--) {
        const int S = 8 >> lev, H = S >> 1;
#pragma unroll
        for (int i = 0; i < S; i++) {
            float t[4], u[4];
#pragma unroll
            for (int j = 0; j < H; j++) {
                float lo = v[i*8+j], hi = v[i*8+j+H];
                t[j] = (lo + hi) * RS2; u[j] = (lo - hi) * RS2;
            }
#pragma unroll
            for (int j = 0; j < H; j++) { v[i*8+2*j] = t[j]; v[i*8+2*j+1] = u[j]; }
        }
#pragma unroll
        for (int j = 0; j < S; j++) {
            float t[4], u[4];
#pragma unroll
            for (int i = 0; i < H; i++) {
                float lo = v[i*8+j], hi = v[(i+H)*8+j];
                t[i] = (lo + hi) * RS2; u[i] = (lo - hi) * RS2;
            }
#pragma unroll
            for (int i = 0; i < H; i++) { v[(2*i)*8+j] = t[i]; v[(2*i+1)*8+j] = u[i]; }
        }
    }
}

// ---- bandlet phase on a thread group (R7 structure, group-local barriers) ----
// SIGMA threads per normal slot (multiple of 32 → nrm warp-uniform); NB blocks.
template<int G, bool LEVEL1, int NB, int SIGMA>
__device__ void bandlet_phase(float* T, int gtid, int base) {
    const int nrm = gtid / SIGMA;
    const int idx = gtid - nrm * SIGMA;
    const bool active = (nrm < 3) && (idx < NB * 8);
    const int s = idx & 7;
    int bd = 0, bh = 0, bw = 0;
    if (active) {
        int bg = idx >> 3;
        int slot = LEVEL1 ? (int)VSLOT[base + bg] : (base + bg + 1);
        if (LEVEL1) { bd = ((slot>>4)&3)*8; bh = ((slot>>2)&3)*8; bw = (slot&3)*8; }
        else        { bd = ((slot>>2)&1)*8; bh = ((slot>>1)&1)*8; bw = (slot&1)*8; }
    }
    float v[64];
    if (active) {
        if (nrm == 0) {
            const float2* p = reinterpret_cast<const float2*>(T + (bd+s)*SD + bh*SH + bw);
#pragma unroll
            for (int i = 0; i < 8; i++)
#pragma unroll
                for (int jp = 0; jp < 4; jp++) {
                    float2 q = p[i*SH2 + jp];
                    v[i*8 + 2*jp] = q.x; v[i*8 + 2*jp + 1] = q.y;
                }
        } else if (nrm == 1) {
            const float2* p = reinterpret_cast<const float2*>(T + bd*SD + (bh+s)*SH + bw);
#pragma unroll
            for (int i = 0; i < 8; i++)
#pragma unroll
                for (int jp = 0; jp < 4; jp++) {
                    float2 q = p[i*SD2 + jp];
                    v[i*8 + 2*jp] = q.x; v[i*8 + 2*jp + 1] = q.y;
                }
        } else {
            const float* p = T + bd*SD + bh*SH + bw + s;
#pragma unroll
            for (int i = 0; i < 8; i++)
#pragma unroll
                for (int j = 0; j < 8; j++) v[i*8+j] = p[i*SD + j*SH];
        }
        pyramid(v);
    }
    gbar<G>();                       // all reads of original band data complete
    if (active && nrm == 0) {
        float2* p = reinterpret_cast<float2*>(T + (bd+s)*SD + bh*SH + bw);
#pragma unroll
        for (int i = 0; i < 8; i++)
#pragma unroll
            for (int jp = 0; jp < 4; jp++)
                p[i*SH2 + jp] = make_float2(v[i*8 + 2*jp], v[i*8 + 2*jp + 1]);
    }
    gbar<G>();                       // n0 visible
    if (active && nrm == 1) {
        float2* p = reinterpret_cast<float2*>(T + bd*SD + (bh+s)*SH + bw);
#pragma unroll
        for (int i = 0; i < 8; i++)
#pragma unroll
            for (int jp = 0; jp < 4; jp++) {
                float2 q = p[i*SD2 + jp];
                q.x += v[i*8 + 2*jp]; q.y += v[i*8 + 2*jp + 1];
                p[i*SD2 + jp] = q;
            }
    }
    gbar<G>();                       // n0+n1 visible
    if (active && nrm == 2) {
        float* p = T + bd*SD + bh*SH + bw + s;
#pragma unroll
        for (int i = 0; i < 8; i++)
#pragma unroll
            for (int j = 0; j < 8; j++)
                p[i*SD + j*SH] = (p[i*SD + j*SH] + v[i*8+j]) * (1.0f / 3.0f);
    }
    // no trailing barrier: the next phase's blocks are disjoint regions
}

__global__ __launch_bounds__(NTHREADS, 1)
void bandlet3d_kernel(const float* __restrict__ x, float* __restrict__ y) {
    float* T = smem;
    float2* T2 = reinterpret_cast<float2*>(smem);
    const int tid = threadIdx.x;

    const int bc = blockIdx.x;
    const int batch = bc / 125;
    const int rem = bc - batch * 125;
    const int td = rem / 25;
    const int th = (rem / 5) % 5;
    const int tw = rem % 5;
    const long long gbase = (long long)batch * 4096000LL
                          + (long long)td * 32 * 25600 + th * 32 * 160 + tw * 32;

    // ---- fused coalesced load + level-1 w-transform ----
    for (int l = tid; l < 8192; l += NTHREADS) {
        int w4 = l & 7, h = (l >> 3) & 31, d = l >> 8;
        float4 q = *reinterpret_cast<const float4*>(x + gbase + d*25600 + h*160 + w4*4);
        float2* p = T2 + d*SD2 + h*SH2;
        p[w4]     = make_float2((q.x + q.y) * RS2, (q.z + q.w) * RS2);
        p[w4 + 8] = make_float2((q.x - q.y) * RS2, (q.z - q.w) * RS2);
    }
    __syncthreads();

    // forward level-1 h and d (full width)
    pass_l1<SD2, SH2, true>(T2, tid); __syncthreads();
    pass_l1<SH2, SD2, true>(T2, tid); __syncthreads();

    // ---- SPLIT: A (warps 0-3) = whole level-2 subtree; B (warps 4-15) = level-1 bandlet ----
    if (tid < 128) {
        const int g = tid;
        // forward level-2 (w, h, d on [0:16)^3 — lll only, disjoint from all band blocks)
        l2_pass_w<true>(T2, g);  barA();
        l2_pass_h<true>(T2, g);  barA();
        l2_pass_d<true>(T2, g);  barA();
        // level-2 bandlet: 7 blocks in phases of 4 + 3 (sigma=32, nrm warp-uniform)
        bandlet_phase<1, false, 4, 32>(T, g, 0);
        bandlet_phase<1, false, 3, 32>(T, g, 4);
        barA();                  // last n2 writes visible before inverse reads
        // inverse level-2 (w, h, d — axis transforms commute)
        l2_pass_w<false>(T2, g); barA();
        l2_pass_h<false>(T2, g); barA();
        l2_pass_d<false>(T2, g);
    } else {
        const int g = tid - 128;
        // level-1 bandlet: 56 blocks in 4 phases of 14 (sigma=128, nrm warp-uniform)
        bandlet_phase<2, true, 14, 128>(T, g, 0);
        bandlet_phase<2, true, 14, 128>(T, g, 14);
        bandlet_phase<2, true, 14, 128>(T, g, 28);
        bandlet_phase<2, true, 14, 128>(T, g, 42);
    }
    __syncthreads();   // join: lll subtree and all band blocks final

    // inverse level-1: d, h, then w fused with the store (full width)
    pass_l1<SH2, SD2, false>(T2, tid); __syncthreads();
    pass_l1<SD2, SH2, false>(T2, tid); __syncthreads();

    // ---- fused inverse level-1 w-transform + coalesced store ----
    for (int l = tid; l < 8192; l += NTHREADS) {
        int w4 = l & 7, h = (l >> 3) & 31, d = l >> 8;
        const float2* p = T2 + d*SD2 + h*SH2;
        float2 lo = p[w4], hi = p[w4 + 8];
        float4 q;
        q.x = (lo.x + hi.x) * RS2; q.y = (lo.x - hi.x) * RS2;
        q.z = (lo.y + hi.y) * RS2; q.w = (lo.y - hi.y) * RS2;
        *reinterpret_cast<float4*>(y + gbase + d*25600 + h*160 + w4*4) = q;
    }
}

extern "C" void kernel_launch(void* const* d_in, const int* in_sizes, int n_in,
                              void* d_out, int out_size) {
    const float* x = (const float*)d_in[0];
    float* y = (float*)d_out;
    (void)in_sizes; (void)n_in; (void)out_size;

    const size_t smem_bytes = (size_t)TILE_F * sizeof(float); // 139520 B
    cudaFuncSetAttribute(bandlet3d_kernel,
                         cudaFuncAttributeMaxDynamicSharedMemorySize, (int)smem_bytes);
    bandlet3d_kernel<<<250, NTHREADS, smem_bytes>>>(x, y);
}

// round 12
// speedup vs baseline: 1.1771x; 1.0432x over previous
#include <cuda_runtime.h>

#define RS2 0.7071067811865476f
#define TAU_V 0.05f

constexpr int SH  = 34;              // even, ≡2 mod 32
constexpr int SD  = 1090;            // even, ≡2 mod 32
constexpr int SH2 = 17;              // strides in float2 units
constexpr int SD2 = 545;
constexpr int TILE_F = 32 * SD;      // 34880 floats = 139520 B
constexpr int NTHREADS = 512;

// valid level-1 band-block slots (slot = d3*16 + h3*4 + w3, excluding lll octant)
__device__ __constant__ unsigned char VSLOT[56] = {
    2,3,6,7,8,9,10,11,12,13,14,15,18,19,22,23,
    24,25,26,27,28,29,30,31,32,33,34,35,36,37,38,39,
    40,41,42,43,44,45,46,47,48,49,50,51,52,53,54,55,
    56,57,58,59,60,61,62,63
};

extern __shared__ float smem[];

__device__ __forceinline__ float2 f2add(float2 a, float2 b) {
    return make_float2((a.x + b.x) * RS2, (a.y + b.y) * RS2);
}
__device__ __forceinline__ float2 f2sub(float2 a, float2 b) {
    return make_float2((a.x - b.x) * RS2, (a.y - b.y) * RS2);
}

// ---- generic h/d pass over pairs of adjacent w columns (float2), in place ----
template<int N, int NA, int NW2, int SBASE2, int SLINE2, bool FWD>
__device__ __forceinline__ void pass_hd(float2* T2, int tid) {
    constexpr int NL = NA * NW2;
    if (NL >= NTHREADS || tid < NL) {
        int a = tid / NW2, wp = tid - a * NW2;
        float2* p = T2 + a * SBASE2 + wp;
        float2 v[N];
#pragma unroll
        for (int k = 0; k < N; k++) v[k] = p[k * SLINE2];
#pragma unroll
        for (int i = 0; i < N / 2; i++) {
            if (FWD) {
                p[i * SLINE2]         = f2add(v[2*i], v[2*i+1]);
                p[(i + N/2) * SLINE2] = f2sub(v[2*i], v[2*i+1]);
            } else {
                p[(2*i) * SLINE2]     = f2add(v[i], v[i + N/2]);
                p[(2*i + 1) * SLINE2] = f2sub(v[i], v[i + N/2]);
            }
        }
    }
}

// ---- fused d pass: level-1 d transform everywhere; level-2 d transform on lll columns ----
// Thread owns the full 32-deep float2 column at (h=a, wpair=wp). lll column: a<16 && wp<8.
template<bool FWD>
__device__ __forceinline__ void pass_d_fused(float2* T2, int tid) {
    const int a = tid >> 4, wp = tid & 15;
    const bool lll = (a < 16) && (wp < 8);
    float2* p = T2 + a * SH2 + wp;
    float2 v[32];
#pragma unroll
    for (int k = 0; k < 32; k++) v[k] = p[k * SD2];
    if (FWD) {
        // L1 fwd: hi -> [16,32); lo compacts into v[0..15]
#pragma unroll
        for (int i = 0; i < 16; i++) p[(16 + i) * SD2] = f2sub(v[2*i], v[2*i+1]);
#pragma unroll
        for (int i = 0; i < 16; i++) v[i] = f2add(v[2*i], v[2*i+1]);
        if (lll) {
            // L2 fwd on the lo half: hi2 -> [8,16); lo2 -> [0,8)
#pragma unroll
            for (int i = 0; i < 8; i++) p[(8 + i) * SD2] = f2sub(v[2*i], v[2*i+1]);
#pragma unroll
            for (int i = 0; i < 8; i++) p[i * SD2] = f2add(v[2*i], v[2*i+1]);
        } else {
#pragma unroll
            for (int i = 0; i < 16; i++) p[i * SD2] = v[i];
        }
    } else {
        if (lll) {
            // composed inverse: L2 inv on [0,16) then L1 inv, algebraically fused
#pragma unroll
            for (int i = 0; i < 8; i++) {
                float2 u0 = f2add(v[i], v[i + 8]);    // u[2i]
                float2 u1 = f2sub(v[i], v[i + 8]);    // u[2i+1]
                p[(4*i)     * SD2] = f2add(u0, v[2*i + 16]);
                p[(4*i + 1) * SD2] = f2sub(u0, v[2*i + 16]);
                p[(4*i + 2) * SD2] = f2add(u1, v[2*i + 17]);
                p[(4*i + 3) * SD2] = f2sub(u1, v[2*i + 17]);
            }
        } else {
#pragma unroll
            for (int i = 0; i < 16; i++) {
                p[(2*i)     * SD2] = f2add(v[i], v[i + 16]);
                p[(2*i + 1) * SD2] = f2sub(v[i], v[i + 16]);
            }
        }
    }
}

// ---- level-2 w pass: 16-long lines along w at (d,h) in [0,16)^2, all-float2 ----
template<bool FWD>
__device__ __forceinline__ void pass_w16(float2* T2, int tid) {
    if (tid < 256) {
        int d = tid >> 4, h = tid & 15;
        float2* p = T2 + d * SD2 + h * SH2;
        float2 q[8];
#pragma unroll
        for (int k = 0; k < 8; k++) q[k] = p[k];
        if (FWD) {
#pragma unroll
            for (int t = 0; t < 4; t++) {
                float2 lo, hi;
                lo.x = (q[2*t].x   + q[2*t].y)   * RS2;
                lo.y = (q[2*t+1].x + q[2*t+1].y) * RS2;
                hi.x = (q[2*t].x   - q[2*t].y)   * RS2;
                hi.y = (q[2*t+1].x - q[2*t+1].y) * RS2;
                p[t] = lo; p[4 + t] = hi;
            }
        } else {
#pragma unroll
            for (int t = 0; t < 4; t++) {
                float2 lo = q[t], hi = q[4 + t];
                p[2*t]     = make_float2((lo.x + hi.x) * RS2, (lo.x - hi.x) * RS2);
                p[2*t + 1] = make_float2((lo.y + hi.y) * RS2, (lo.y - hi.y) * RS2);
            }
        }
    }
}

// ---- 2D Haar pyramid fwd + soft-threshold + inv on v[64] in registers ----
__device__ __forceinline__ void pyramid(float* v) {
#pragma unroll
    for (int lev = 0; lev < 3; lev++) {
        const int S = 8 >> lev, H = S >> 1;
#pragma unroll
        for (int j = 0; j < S; j++) {
            float t[4], u[4];
#pragma unroll
            for (int i = 0; i < H; i++) {
                float a = v[(2*i)*8+j], b = v[(2*i+1)*8+j];
                t[i] = (a + b) * RS2; u[i] = (a - b) * RS2;
            }
#pragma unroll
            for (int i = 0; i < H; i++) { v[i*8+j] = t[i]; v[(i+H)*8+j] = u[i]; }
        }
#pragma unroll
        for (int i = 0; i < S; i++) {
            float t[4], u[4];
#pragma unroll
            for (int j = 0; j < H; j++) {
                float a = v[i*8+2*j], b = v[i*8+2*j+1];
                t[j] = (a + b) * RS2; u[j] = (a - b) * RS2;
            }
#pragma unroll
            for (int j = 0; j < H; j++) { v[i*8+j] = t[j]; v[i*8+j+H] = u[j]; }
        }
    }
    // soft threshold (keep DC): v -= clamp(v, -tau, tau)  — identical semantics, 2 ops
#pragma unroll
    for (int e = 1; e < 64; e++)
        v[e] = v[e] - fminf(fmaxf(v[e], -TAU_V), TAU_V);
#pragma unroll
    for (int lev = 2; lev >= 0; lev--) {
        const int S = 8 >> lev, H = S >> 1;
#pragma unroll
        for (int i = 0; i < S; i++) {
            float t[4], u[4];
#pragma unroll
            for (int j = 0; j < H; j++) {
                float lo = v[i*8+j], hi = v[i*8+j+H];
                t[j] = (lo + hi) * RS2; u[j] = (lo - hi) * RS2;
            }
#pragma unroll
            for (int j = 0; j < H; j++) { v[i*8+2*j] = t[j]; v[i*8+2*j+1] = u[j]; }
        }
#pragma unroll
        for (int j = 0; j < S; j++) {
            float t[4], u[4];
#pragma unroll
            for (int i = 0; i < H; i++) {
                float lo = v[i*8+j], hi = v[(i+H)*8+j];
                t[i] = (lo + hi) * RS2; u[i] = (lo - hi) * RS2;
            }
#pragma unroll
            for (int i = 0; i < H; i++) { v[(2*i)*8+j] = t[i]; v[(2*i+1)*8+j] = u[i]; }
        }
    }
}

// R7-style group: compute, then 3 ordered in-T writeback phases (n0 store, n1 +=, n2 merge/3).
// No trailing barrier — successive groups touch disjoint block regions.
__device__ __forceinline__ void bandlet_group(float* T, int nrm, bool active,
                                              int bd, int bh, int bw, int s) {
    float v[64];
    if (active) {
        if (nrm == 0) {
            const float2* p = reinterpret_cast<const float2*>(T + (bd+s)*SD + bh*SH + bw);
#pragma unroll
            for (int i = 0; i < 8; i++)
#pragma unroll
                for (int jp = 0; jp < 4; jp++) {
                    float2 q = p[i*SH2 + jp];
                    v[i*8 + 2*jp] = q.x; v[i*8 + 2*jp + 1] = q.y;
                }
        } else if (nrm == 1) {
            const float2* p = reinterpret_cast<const float2*>(T + bd*SD + (bh+s)*SH + bw);
#pragma unroll
            for (int i = 0; i < 8; i++)
#pragma unroll
                for (int jp = 0; jp < 4; jp++) {
                    float2 q = p[i*SD2 + jp];
                    v[i*8 + 2*jp] = q.x; v[i*8 + 2*jp + 1] = q.y;
                }
        } else {
            const float* p = T + bd*SD + bh*SH + bw + s;
#pragma unroll
            for (int i = 0; i < 8; i++)
#pragma unroll
                for (int j = 0; j < 8; j++) v[i*8+j] = p[i*SD + j*SH];
        }
        pyramid(v);
    }
    __syncthreads();
    if (active && nrm == 0) {
        float2* p = reinterpret_cast<float2*>(T + (bd+s)*SD + bh*SH + bw);
#pragma unroll
        for (int i = 0; i < 8; i++)
#pragma unroll
            for (int jp = 0; jp < 4; jp++)
                p[i*SH2 + jp] = make_float2(v[i*8 + 2*jp], v[i*8 + 2*jp + 1]);
    }
    __syncthreads();
    if (active && nrm == 1) {
        float2* p = reinterpret_cast<float2*>(T + bd*SD + (bh+s)*SH + bw);
#pragma unroll
        for (int i = 0; i < 8; i++)
#pragma unroll
            for (int jp = 0; jp < 4; jp++) {
                float2 q = p[i*SD2 + jp];
                q.x += v[i*8 + 2*jp]; q.y += v[i*8 + 2*jp + 1];
                p[i*SD2 + jp] = q;
            }
    }
    __syncthreads();
    if (active && nrm == 2) {
        float* p = T + bd*SD + bh*SH + bw + s;
#pragma unroll
        for (int i = 0; i < 8; i++)
#pragma unroll
            for (int j = 0; j < 8; j++)
                p[i*SD + j*SH] = (p[i*SD + j*SH] + v[i*8+j]) * (1.0f / 3.0f);
    }
}

__global__ __launch_bounds__(NTHREADS, 1)
void bandlet3d_kernel(const float* __restrict__ x, float* __restrict__ y) {
    float* T = smem;
    float2* T2 = reinterpret_cast<float2*>(smem);
    const int tid = threadIdx.x;

    const int bc = blockIdx.x;
    const int batch = bc / 125;
    const int rem = bc - batch * 125;
    const int td = rem / 25;
    const int th = (rem / 5) % 5;
    const int tw = rem % 5;
    const long long gbase = (long long)batch * 4096000LL
                          + (long long)td * 32 * 25600 + th * 32 * 160 + tw * 32;

    // ---- fused coalesced load + level-1 w-transform ----
    for (int l = tid; l < 8192; l += NTHREADS) {
        int w4 = l & 7, h = (l >> 3) & 31, d = l >> 8;
        float4 q = *reinterpret_cast<const float4*>(x + gbase + d*25600 + h*160 + w4*4);
        float2* p = T2 + d*SD2 + h*SH2;
        p[w4]     = make_float2((q.x + q.y) * RS2, (q.z + q.w) * RS2);
        p[w4 + 8] = make_float2((q.x - q.y) * RS2, (q.z - q.w) * RS2);
    }
    __syncthreads();

    // forward level-1 h, then fused level-1 d + level-2 d (lll columns)
    pass_hd<32, 32, 16, SD2, SH2, true>(T2, tid); __syncthreads();
    pass_d_fused<true>(T2, tid);                  __syncthreads();

    // ---- level-1 bandlet: 56 blocks in groups of 21/21/14 ----
    for (int g = 0; g < 3; g++) {
        const int base = g * 21;
        const int nblk = (g == 2) ? 14 : 21;
        const int ntask = nblk * 8;
        int nrm = 3, s = 0, bd = 0, bh = 0, bw = 0;
        bool active = (tid < 3 * ntask);
        if (active) {
            nrm = tid / ntask;
            int r = tid - nrm * ntask;
            int bg = r >> 3; s = r & 7;
            int slot = VSLOT[base + bg];
            bd = ((slot >> 4) & 3) * 8;
            bh = ((slot >> 2) & 3) * 8;
            bw = (slot & 3) * 8;
        }
        bandlet_group(T, nrm, active, bd, bh, bw, s);
    }
    // no barrier: remaining fwd level-2 passes touch only the lll region (disjoint)

    // forward level-2 h and w (d already applied in the fused pass)
    pass_hd<16, 16, 8, SD2, SH2, true>(T2, tid);  __syncthreads();
    pass_w16<true>(T2, tid);                      __syncthreads();

    // ---- level-2 bandlet: 7 blocks, 168 tasks ----
    {
        int nrm = 3, s = 0, bd = 0, bh = 0, bw = 0;
        bool active = (tid < 168);
        if (active) {
            nrm = tid / 56;
            int r = tid - nrm * 56;
            int bg = r >> 3; s = r & 7;
            int slot = bg + 1;
            bd = ((slot >> 2) & 1) * 8;
            bh = ((slot >> 1) & 1) * 8;
            bw = (slot & 1) * 8;
        }
        bandlet_group(T, nrm, active, bd, bh, bw, s);
    }
    __syncthreads();   // inverse level-2 reads the band blocks just written

    // inverse level-2 w and h (d deferred into the fused inverse pass)
    pass_w16<false>(T2, tid);                      __syncthreads();
    pass_hd<16, 16, 8, SD2, SH2, false>(T2, tid);  __syncthreads();

    // fused inverse: level-2 d (lll columns) + level-1 d; then h; then w fused with store
    pass_d_fused<false>(T2, tid);                  __syncthreads();
    pass_hd<32, 32, 16, SD2, SH2, false>(T2, tid); __syncthreads();

    // ---- fused inverse level-1 w-transform + coalesced store ----
    for (int l = tid; l < 8192; l += NTHREADS) {
        int w4 = l & 7, h = (l >> 3) & 31, d = l >> 8;
        const float2* p = T2 + d*SD2 + h*SH2;
        float2 lo = p[w4], hi = p[w4 + 8];
        float4 q;
        q.x = (lo.x + hi.x) * RS2; q.y = (lo.x - hi.x) * RS2;
        q.z = (lo.y + hi.y) * RS2; q.w = (lo.y - hi.y) * RS2;
        *reinterpret_cast<float4*>(y + gbase + d*25600 + h*160 + w4*4) = q;
    }
}

extern "C" void kernel_launch(void* const* d_in, const int* in_sizes, int n_in,
                              void* d_out, int out_size) {
    const float* x = (const float*)d_in[0];
    float* y = (float*)d_out;
    (void)in_sizes; (void)n_in; (void)out_size;

    const size_t smem_bytes = (size_t)TILE_F * sizeof(float); // 139520 B
    cudaFuncSetAttribute(bandlet3d_kernel,
                         cudaFuncAttributeMaxDynamicSharedMemorySize, (int)smem_bytes);
    bandlet3d_kernel<<<250, NTHREADS, smem_bytes>>>(x, y);
}